// round 8
// baseline (speedup 1.0000x reference)
#include <cuda_runtime.h>
#include <cuda_bf16.h>
#include <math.h>
#include <cstdint>

#define NN 50000
#define SEQL 52
#define FIN 16
#define HD 128
#define H3 384
#define NE 800000
#define ET (NE + NN)
#define NEG 0.2f

// ---------------- static scratch (~110 MB) ----------------
static __device__ float d_xp[(size_t)NN * HD];
static __device__ float d_as[NN];
static __device__ float d_ad[NN];
static __device__ unsigned short d_sph[(size_t)NN * HD];   // spatial hi bf16
static __device__ unsigned short d_spl[(size_t)NN * HD];   // spatial lo bf16
static __device__ float d_h[(size_t)NN * HD];
static __device__ unsigned short d_hh[(size_t)NN * HD];    // h hi bf16
static __device__ unsigned short d_hl[(size_t)NN * HD];    // h lo bf16
static __device__ unsigned short d_wih_h[H3 * HD], d_wih_l[H3 * HD];
static __device__ unsigned short d_whh_h[H3 * HD], d_whh_l[H3 * HD];
static __device__ int   d_cnt[NN];
static __device__ int   d_rowptr[NN + 1];
static __device__ int   d_cur[NN];
static __device__ int   d_csrc[ET];

__device__ __forceinline__ uint32_t s2u(const void* p) {
    uint32_t a;
    asm("{ .reg .u64 t; cvta.to.shared.u64 t, %1; cvt.u32.u64 %0, t; }"
        : "=r"(a) : "l"(p));
    return a;
}

__device__ __forceinline__ void split_bf16(float v, unsigned short& hi,
                                           unsigned short& lo) {
    __nv_bfloat16 h = __float2bfloat16_rn(v);
    float rem = v - __bfloat162float(h);
    __nv_bfloat16 l = __float2bfloat16_rn(rem);
    hi = __bfloat16_as_ushort(h);
    lo = __bfloat16_as_ushort(l);
}

__device__ __forceinline__ void ldsm4(uint32_t* r, uint32_t addr) {
    asm volatile("ldmatrix.sync.aligned.m8n8.x4.shared.b16 {%0,%1,%2,%3}, [%4];"
                 : "=r"(r[0]), "=r"(r[1]), "=r"(r[2]), "=r"(r[3]) : "r"(addr));
}
__device__ __forceinline__ void mma16816(float* c, const uint32_t* a,
                                         uint32_t b0, uint32_t b1) {
    asm volatile(
        "mma.sync.aligned.m16n8k16.row.col.f32.bf16.bf16.f32 "
        "{%0,%1,%2,%3}, {%4,%5,%6,%7}, {%8,%9}, {%0,%1,%2,%3};"
        : "+f"(c[0]), "+f"(c[1]), "+f"(c[2]), "+f"(c[3])
        : "r"(a[0]), "r"(a[1]), "r"(a[2]), "r"(a[3]), "r"(b0), "r"(b1));
}

// ---------------- CSR build ----------------
__global__ void k_hist(const int* __restrict__ ei) {
    int idx = blockIdx.x * blockDim.x + threadIdx.x;
    if (idx < NE) {
        atomicAdd(&d_cnt[ei[NE + idx]], 1);
    } else if (idx < ET) {
        atomicAdd(&d_cnt[idx - NE], 1);
    }
}

__global__ void k_scan() {
    __shared__ int sh[1024];
    __shared__ int carry;
    int tid = threadIdx.x;
    if (tid == 0) carry = 0;
    __syncthreads();
    for (int base = 0; base < NN; base += 1024) {
        int v = (base + tid < NN) ? d_cnt[base + tid] : 0;
        sh[tid] = v;
        __syncthreads();
        for (int off = 1; off < 1024; off <<= 1) {
            int t2 = (tid >= off) ? sh[tid - off] : 0;
            __syncthreads();
            sh[tid] += t2;
            __syncthreads();
        }
        int inc = sh[tid];
        int ex = inc - v;
        if (base + tid < NN) {
            d_rowptr[base + tid] = carry + ex;
            d_cur[base + tid] = carry + ex;
        }
        int tot = sh[1023];
        __syncthreads();
        if (tid == 0) carry += tot;
        __syncthreads();
    }
    if (tid == 0) d_rowptr[NN] = carry;
}

__global__ void k_scatter(const int* __restrict__ ei) {
    int idx = blockIdx.x * blockDim.x + threadIdx.x;
    if (idx < NE) {
        int s = ei[idx];
        int d = ei[NE + idx];
        int p = atomicAdd(&d_cur[d], 1);
        d_csrc[p] = s;
    } else if (idx < ET) {
        int i = idx - NE;
        int p = atomicAdd(&d_cur[i], 1);
        d_csrc[p] = i;
    }
}

// ---------------- weight split to hi/lo bf16 ----------------
__global__ void k_wconv(const float* __restrict__ Wih,
                        const float* __restrict__ Whh) {
    int idx = blockIdx.x * blockDim.x + threadIdx.x;
    if (idx < H3 * HD) {
        split_bf16(Wih[idx], d_wih_h[idx], d_wih_l[idx]);
        split_bf16(Whh[idx], d_whh_h[idx], d_whh_l[idx]);
    }
}

// ---------------- xp = x_t @ Wg + attention dots ----------------
__global__ void k_xp(const float* __restrict__ x_t,
                     const float* __restrict__ Wg,
                     const float* __restrict__ att_s,
                     const float* __restrict__ att_d) {
    __shared__ float sWg[FIN * HD];
    __shared__ float sas[HD], sad[HD];
    __shared__ float sx[2][FIN];
    __shared__ float red_s[2][4], red_d[2][4];
    int tid = threadIdx.x;  // 256
    for (int i = tid; i < FIN * HD; i += 256) sWg[i] = Wg[i];
    if (tid < HD) { sas[tid] = att_s[tid]; sad[tid] = att_d[tid]; }
    int row = blockIdx.x * 2 + (tid / HD);
    int lr = tid / HD;
    int j = tid % HD;
    if (j < FIN && row < NN) sx[lr][j] = x_t[(size_t)row * FIN + j];
    __syncthreads();
    if (row >= NN) return;
    float acc = 0.f;
#pragma unroll
    for (int k = 0; k < FIN; k++) acc += sx[lr][k] * sWg[k * HD + j];
    d_xp[(size_t)row * HD + j] = acc;
    float vs = acc * sas[j];
    float vd = acc * sad[j];
#pragma unroll
    for (int o = 16; o > 0; o >>= 1) {
        vs += __shfl_down_sync(0xffffffffu, vs, o);
        vd += __shfl_down_sync(0xffffffffu, vd, o);
    }
    int lane = tid & 31;
    int w = (tid >> 5) & 3;
    if (lane == 0) { red_s[lr][w] = vs; red_d[lr][w] = vd; }
    __syncthreads();
    if (j == 0) {
        d_as[row] = red_s[lr][0] + red_s[lr][1] + red_s[lr][2] + red_s[lr][3];
        d_ad[row] = red_d[lr][0] + red_d[lr][1] + red_d[lr][2] + red_d[lr][3];
    }
}

// ---------------- GAT aggregate: warp/row online softmax; bf16 hi/lo out -----
__global__ void k_gat(const float* __restrict__ bias_g) {
    int warp = threadIdx.x >> 5, lane = threadIdx.x & 31;
    int row = blockIdx.x * 8 + warp;
    if (row >= NN) return;
    float ad = d_ad[row];
    int r0 = d_rowptr[row], r1 = d_rowptr[row + 1];
    float m = -1e30f, s = 0.f;
    float ax = 0.f, ay = 0.f, az = 0.f, aw = 0.f;
    int c = lane * 4;
    for (int e = r0; e < r1; e++) {
        int src = d_csrc[e];
        float ev = d_as[src] + ad;
        ev = (ev >= 0.f) ? ev : NEG * ev;
        float mn = fmaxf(m, ev);
        float sc = expf(m - mn);
        float w = expf(ev - mn);
        s = s * sc + w;
        float4 v = *(const float4*)(d_xp + (size_t)src * HD + c);
        ax = ax * sc + w * v.x;
        ay = ay * sc + w * v.y;
        az = az * sc + w * v.z;
        aw = aw * sc + w * v.w;
        m = mn;
    }
    float inv = 1.f / s;
    float4 b = *(const float4*)(bias_g + c);
    float4 o;
    o.x = fmaxf(ax * inv + b.x, 0.f);
    o.y = fmaxf(ay * inv + b.y, 0.f);
    o.z = fmaxf(az * inv + b.z, 0.f);
    o.w = fmaxf(aw * inv + b.w, 0.f);
    unsigned short h0, h1, h2, h3, l0, l1, l2, l3;
    split_bf16(o.x, h0, l0);
    split_bf16(o.y, h1, l1);
    split_bf16(o.z, h2, l2);
    split_bf16(o.w, h3, l3);
    size_t off = (size_t)row * HD + c;
    uint2 ph = make_uint2((uint32_t)h0 | ((uint32_t)h1 << 16),
                          (uint32_t)h2 | ((uint32_t)h3 << 16));
    uint2 pl = make_uint2((uint32_t)l0 | ((uint32_t)l1 << 16),
                          (uint32_t)l2 | ((uint32_t)l3 << 16));
    *(uint2*)(d_sph + off) = ph;
    *(uint2*)(d_spl + off) = pl;
}

// ---------------- fused GEMM x2 + GRU: h = GRU(spatial, h) -------------------
// Per CTA: 64 rows. 3 column chunks (r, z, n gates). Split-bf16 3-pass HMMA.
// r,z gate fragments live in registers across chunks (identical warp layout).
#define TSTRIDE 272                          // padded row stride bytes
#define A_TILE (64 * TSTRIDE)                // 17408
#define B_TILE (128 * TSTRIDE)               // 34816
#define SM_ASP_H 0
#define SM_ASP_L (A_TILE)
#define SM_AH_H  (2 * A_TILE)
#define SM_AH_L  (3 * A_TILE)
#define SM_B0    (4 * A_TILE)                // 69632
#define SM_WIH_H (SM_B0)
#define SM_WIH_L (SM_B0 + B_TILE)
#define SM_WHH_H (SM_B0 + 2 * B_TILE)
#define SM_WHH_L (SM_B0 + 3 * B_TILE)
#define FUSED_SMEM (SM_B0 + 4 * B_TILE)      // 208896

__global__ void __launch_bounds__(256, 1)
k_fused(const uint4* __restrict__ Asp_h, const uint4* __restrict__ Asp_l,
        const uint4* __restrict__ Ah_h, const uint4* __restrict__ Ah_l,
        const uint4* __restrict__ Wih_h, const uint4* __restrict__ Wih_l,
        const uint4* __restrict__ Whh_h, const uint4* __restrict__ Whh_l,
        const float* __restrict__ b_ih, const float* __restrict__ b_hh,
        float* __restrict__ Hout, unsigned short* __restrict__ Hh,
        unsigned short* __restrict__ Hl) {
    extern __shared__ char smem[];
    uint32_t sb = s2u(smem);
    int tid = threadIdx.x, wid = tid >> 5, lane = tid & 31;
    int m0 = blockIdx.x * 64;

    // load A tiles (spatial hi/lo, h hi/lo), 64 rows x 128 bf16
    for (int idx = tid; idx < 1024; idx += 256) {
        int r = idx >> 4, q = idx & 15;
        int gm = m0 + r;
        uint4 v0 = make_uint4(0, 0, 0, 0), v1 = v0, v2 = v0, v3 = v0;
        if (gm < NN) {
            size_t go = (size_t)gm * 16 + q;
            v0 = Asp_h[go]; v1 = Asp_l[go]; v2 = Ah_h[go]; v3 = Ah_l[go];
        }
        char* dst = smem + r * TSTRIDE + q * 16;
        *(uint4*)(dst + SM_ASP_H) = v0;
        *(uint4*)(dst + SM_ASP_L) = v1;
        *(uint4*)(dst + SM_AH_H) = v2;
        *(uint4*)(dst + SM_AH_L) = v3;
    }

    // warp tiling: 2 (M) x 4 (N) warps; warp tile 32x32 within 64x128 chunk
    int warp_m = (wid >> 2) * 32;
    int warp_n = (wid & 3) * 32;
    int rowA = (lane & 7) + ((lane >> 3) & 1) * 8;
    int kofA = ((lane >> 4) & 1) * 16;
    int rowB = (lane & 7) + ((lane >> 4) & 1) * 8;
    int kofB = ((lane >> 3) & 1) * 16;
    uint32_t aOff[2], bOff[2];
#pragma unroll
    for (int mi = 0; mi < 2; mi++)
        aOff[mi] = sb + (warp_m + mi * 16 + rowA) * TSTRIDE + kofA;
#pragma unroll
    for (int p = 0; p < 2; p++)
        bOff[p] = sb + (warp_n + p * 16 + rowB) * TSTRIDE + kofB;

    int trow = lane >> 2, tcol = (lane & 3) * 2;

    float r_reg[2][4][4], z_reg[2][4][4];

    for (int cb = 0; cb < 3; cb++) {
        __syncthreads();   // prior compute done (and A stores visible on cb=0)
        // load B: Wih hi/lo + Whh hi/lo, rows cb*128..cb*128+127
        for (int idx = tid; idx < 2048; idx += 256) {
            int r = idx >> 4, q = idx & 15;
            size_t go = (size_t)(cb * 128 + r) * 16 + q;
            char* dst = smem + r * TSTRIDE + q * 16;
            *(uint4*)(dst + SM_WIH_H) = Wih_h[go];
            *(uint4*)(dst + SM_WIH_L) = Wih_l[go];
            *(uint4*)(dst + SM_WHH_H) = Whh_h[go];
            *(uint4*)(dst + SM_WHH_L) = Whh_l[go];
        }
        __syncthreads();

        float accs[2][4][4], acch[2][4][4];
#pragma unroll
        for (int i = 0; i < 2; i++)
#pragma unroll
            for (int j = 0; j < 4; j++)
#pragma unroll
                for (int k = 0; k < 4; k++) { accs[i][j][k] = 0.f; acch[i][j][k] = 0.f; }

#pragma unroll
        for (int ks = 0; ks < 8; ks++) {
            // --- spatial GEMM: accs += Asp(h,l) x Wih(h,l), 3 passes ---
            {
                uint32_t ah[2][4], al[2][4], bh[2][4], bl[2][4];
#pragma unroll
                for (int mi = 0; mi < 2; mi++) {
                    uint32_t ad = aOff[mi] + ks * 32;
                    ldsm4(ah[mi], ad + SM_ASP_H);
                    ldsm4(al[mi], ad + SM_ASP_L);
                }
#pragma unroll
                for (int p = 0; p < 2; p++) {
                    uint32_t bd = bOff[p] + ks * 32;
                    ldsm4(bh[p], bd + SM_WIH_H);
                    ldsm4(bl[p], bd + SM_WIH_L);
                }
#pragma unroll
                for (int mi = 0; mi < 2; mi++)
#pragma unroll
                    for (int p = 0; p < 2; p++)
#pragma unroll
                        for (int sub = 0; sub < 2; sub++) {
                            float* c = accs[mi][p * 2 + sub];
                            uint32_t b0 = bh[p][sub * 2], b1 = bh[p][sub * 2 + 1];
                            mma16816(c, ah[mi], b0, b1);
                            mma16816(c, al[mi], b0, b1);
                            mma16816(c, ah[mi], bl[p][sub * 2], bl[p][sub * 2 + 1]);
                        }
            }
            // --- hidden GEMM: acch += Ah(h,l) x Whh(h,l), 3 passes ---
            {
                uint32_t ah[2][4], al[2][4], bh[2][4], bl[2][4];
#pragma unroll
                for (int mi = 0; mi < 2; mi++) {
                    uint32_t ad = aOff[mi] + ks * 32;
                    ldsm4(ah[mi], ad + SM_AH_H);
                    ldsm4(al[mi], ad + SM_AH_L);
                }
#pragma unroll
                for (int p = 0; p < 2; p++) {
                    uint32_t bd = bOff[p] + ks * 32;
                    ldsm4(bh[p], bd + SM_WHH_H);
                    ldsm4(bl[p], bd + SM_WHH_L);
                }
#pragma unroll
                for (int mi = 0; mi < 2; mi++)
#pragma unroll
                    for (int p = 0; p < 2; p++)
#pragma unroll
                        for (int sub = 0; sub < 2; sub++) {
                            float* c = acch[mi][p * 2 + sub];
                            uint32_t b0 = bh[p][sub * 2], b1 = bh[p][sub * 2 + 1];
                            mma16816(c, ah[mi], b0, b1);
                            mma16816(c, al[mi], b0, b1);
                            mma16816(c, ah[mi], bl[p][sub * 2], bl[p][sub * 2 + 1]);
                        }
            }
        }

        // --- per-chunk gate epilogue (registers only for cb 0,1) ---
#pragma unroll
        for (int mi = 0; mi < 2; mi++) {
#pragma unroll
            for (int nj = 0; nj < 4; nj++) {
                int nc = warp_n + nj * 8 + tcol;           // 0..127 within chunk
                int gc = cb * 128 + nc;                     // gate column
                float2 bi = *(const float2*)(b_ih + gc);
                float2 bh2 = *(const float2*)(b_hh + gc);
#pragma unroll
                for (int k = 0; k < 4; k++) {
                    float bi_v = (k & 1) ? bi.y : bi.x;
                    float bh_v = (k & 1) ? bh2.y : bh2.x;
                    float gsum = accs[mi][nj][k] + bi_v + acch[mi][nj][k] + bh_v;
                    if (cb == 0) {
                        r_reg[mi][nj][k] = 1.f / (1.f + expf(-gsum));
                    } else if (cb == 1) {
                        z_reg[mi][nj][k] = 1.f / (1.f + expf(-gsum));
                    } else {
                        int gm = m0 + warp_m + mi * 16 + trow + ((k >> 1) * 8);
                        if (gm < NN && (k & 1) == 0) {
                            // handle pair (k, k+1) together for vector store
                        }
                    }
                }
                if (cb == 2) {
#pragma unroll
                    for (int half = 0; half < 2; half++) {  // k pairs {0,1},{2,3}
                        int gm = m0 + warp_m + mi * 16 + trow + half * 8;
                        if (gm >= NN) continue;
                        float in0 = accs[mi][nj][half * 2 + 0] + bi.x;
                        float in1 = accs[mi][nj][half * 2 + 1] + bi.y;
                        float hn0 = acch[mi][nj][half * 2 + 0] + bh2.x;
                        float hn1 = acch[mi][nj][half * 2 + 1] + bh2.y;
                        float r0 = r_reg[mi][nj][half * 2 + 0];
                        float r1 = r_reg[mi][nj][half * 2 + 1];
                        float z0 = z_reg[mi][nj][half * 2 + 0];
                        float z1 = z_reg[mi][nj][half * 2 + 1];
                        float n0 = tanhf(in0 + r0 * hn0);
                        float n1 = tanhf(in1 + r1 * hn1);
                        size_t ho = (size_t)gm * HD + nc;
                        float2 hp = *(const float2*)(Hout + ho);
                        float o0 = (1.f - z0) * n0 + z0 * hp.x;
                        float o1 = (1.f - z1) * n1 + z1 * hp.y;
                        *(float2*)(Hout + ho) = make_float2(o0, o1);
                        unsigned short hh0, hl0, hh1, hl1;
                        split_bf16(o0, hh0, hl0);
                        split_bf16(o1, hh1, hl1);
                        *(uint32_t*)(Hh + ho) =
                            (uint32_t)hh0 | ((uint32_t)hh1 << 16);
                        *(uint32_t*)(Hl + ho) =
                            (uint32_t)hl0 | ((uint32_t)hl1 << 16);
                    }
                }
            }
        }
    }
}

// ---------------- final fc ----------------
__global__ void k_fc(const float* __restrict__ Wfc,
                     const float* __restrict__ bfc,
                     float* __restrict__ out) {
    int warp = threadIdx.x >> 5, lane = threadIdx.x & 31;
    int row = blockIdx.x * 8 + warp;
    if (row >= NN) return;
    float4 hv = *(const float4*)(d_h + (size_t)row * HD + lane * 4);
    float4 wv = *(const float4*)(Wfc + lane * 4);
    float v = hv.x * wv.x + hv.y * wv.y + hv.z * wv.z + hv.w * wv.w;
#pragma unroll
    for (int o = 16; o > 0; o >>= 1) v += __shfl_down_sync(0xffffffffu, v, o);
    if (lane == 0) out[row] = v + bfc[0];
}

// ---------------- launch ----------------
extern "C" void kernel_launch(void* const* d_in, const int* in_sizes, int n_in,
                              void* d_out, int out_size) {
    const float* x_seq   = (const float*)d_in[0];
    const int*   ei      = (const int*)d_in[1];
    const float* Wg      = (const float*)d_in[2];
    const float* att_src = (const float*)d_in[3];
    const float* att_dst = (const float*)d_in[4];
    const float* bias_g  = (const float*)d_in[5];
    const float* W_ih    = (const float*)d_in[6];
    const float* W_hh    = (const float*)d_in[7];
    const float* b_ih    = (const float*)d_in[8];
    const float* b_hh    = (const float*)d_in[9];
    const float* W_fc    = (const float*)d_in[10];
    const float* b_fc    = (const float*)d_in[11];
    float* out = (float*)d_out;

    void *p_cnt, *p_h, *p_hh, *p_hl, *p_sph, *p_spl;
    void *p_wih_h, *p_wih_l, *p_whh_h, *p_whh_l;
    cudaGetSymbolAddress(&p_cnt, d_cnt);
    cudaGetSymbolAddress(&p_h, d_h);
    cudaGetSymbolAddress(&p_hh, d_hh);
    cudaGetSymbolAddress(&p_hl, d_hl);
    cudaGetSymbolAddress(&p_sph, d_sph);
    cudaGetSymbolAddress(&p_spl, d_spl);
    cudaGetSymbolAddress(&p_wih_h, d_wih_h);
    cudaGetSymbolAddress(&p_wih_l, d_wih_l);
    cudaGetSymbolAddress(&p_whh_h, d_whh_h);
    cudaGetSymbolAddress(&p_whh_l, d_whh_l);

    cudaFuncSetAttribute(k_fused, cudaFuncAttributeMaxDynamicSharedMemorySize,
                         FUSED_SMEM);

    cudaMemsetAsync(p_cnt, 0, NN * sizeof(int));
    cudaMemsetAsync(p_h, 0, (size_t)NN * HD * sizeof(float));
    cudaMemsetAsync(p_hh, 0, (size_t)NN * HD * sizeof(unsigned short));
    cudaMemsetAsync(p_hl, 0, (size_t)NN * HD * sizeof(unsigned short));

    k_wconv<<<(H3 * HD + 255) / 256, 256>>>(W_ih, W_hh);
    k_hist<<<(ET + 255) / 256, 256>>>(ei);
    k_scan<<<1, 1024>>>();
    k_scatter<<<(ET + 255) / 256, 256>>>(ei);

    int fgrid = (NN + 63) / 64;
    for (int t = 0; t < SEQL; t++) {
        k_xp<<<(NN + 1) / 2, 256>>>(x_seq + (size_t)t * NN * FIN, Wg,
                                    att_src, att_dst);
        k_gat<<<(NN + 7) / 8, 256>>>(bias_g);
        k_fused<<<fgrid, 256, FUSED_SMEM>>>(
            (const uint4*)p_sph, (const uint4*)p_spl,
            (const uint4*)p_hh, (const uint4*)p_hl,
            (const uint4*)p_wih_h, (const uint4*)p_wih_l,
            (const uint4*)p_whh_h, (const uint4*)p_whh_l,
            b_ih, b_hh,
            (float*)p_h, (unsigned short*)p_hh, (unsigned short*)p_hl);
    }

    k_fc<<<(NN + 7) / 8, 256>>>(W_fc, b_fc, out);
}